// round 1
// baseline (speedup 1.0000x reference)
#include <cuda_runtime.h>
#include <math.h>

#define N_NODES 4096
#define N_EDGES 65536
#define N_BATCH 256
#define HID 64

// ---------------- scratch (no allocations allowed) ----------------
__device__ int g_deg_in[N_NODES];
__device__ int g_deg_out[N_NODES];
__device__ int g_cursor[N_NODES];
__device__ int g_rowptr[N_NODES + 1];
__device__ unsigned short g_col[N_EDGES];
__device__ float g_csrc[N_NODES];
__device__ float g_cdst[N_NODES];

// ---------------- CSR construction ----------------
__global__ void k_zero() {
    int i = blockIdx.x * blockDim.x + threadIdx.x;
    if (i < N_NODES) { g_deg_in[i] = 0; g_deg_out[i] = 0; g_cursor[i] = 0; }
}

__global__ void k_deg(const int* __restrict__ src, const int* __restrict__ dst) {
    int e = blockIdx.x * blockDim.x + threadIdx.x;
    if (e < N_EDGES) {
        atomicAdd(&g_deg_out[src[e]], 1);
        atomicAdd(&g_deg_in[dst[e]], 1);
    }
}

__global__ void k_scan() {
    __shared__ int ssum[1024];
    int t = threadIdx.x;
    int d0 = g_deg_in[4 * t + 0];
    int d1 = g_deg_in[4 * t + 1];
    int d2 = g_deg_in[4 * t + 2];
    int d3 = g_deg_in[4 * t + 3];
    int s = d0 + d1 + d2 + d3;
    ssum[t] = s;
    __syncthreads();
    // Hillis-Steele inclusive scan over 1024 thread sums
    for (int off = 1; off < 1024; off <<= 1) {
        int v = (t >= off) ? ssum[t - off] : 0;
        __syncthreads();
        ssum[t] += v;
        __syncthreads();
    }
    int excl = ssum[t] - s;
    g_rowptr[4 * t + 0] = excl;
    g_rowptr[4 * t + 1] = excl + d0;
    g_rowptr[4 * t + 2] = excl + d0 + d1;
    g_rowptr[4 * t + 3] = excl + d0 + d1 + d2;
    if (t == 1023) g_rowptr[N_NODES] = ssum[1023];
    for (int n = t; n < N_NODES; n += 1024) {
        g_csrc[n] = rsqrtf(fmaxf((float)g_deg_out[n], 1.0f));
        g_cdst[n] = rsqrtf(fmaxf((float)g_deg_in[n], 1.0f));
    }
}

__global__ void k_scatter(const int* __restrict__ src, const int* __restrict__ dst) {
    int e = blockIdx.x * blockDim.x + threadIdx.x;
    if (e < N_EDGES) {
        int d = dst[e];
        int pos = atomicAdd(&g_cursor[d], 1);
        g_col[g_rowptr[d] + pos] = (unsigned short)src[e];
    }
}

// Sort each node's neighbor segment: makes fp32 accumulation order a pure
// function of the input (atomic scatter order is not deterministic), and
// improves gather locality. Segments are ~16 entries (Poisson), insertion
// sort is cheap.
__global__ void k_sort() {
    int n = blockIdx.x * blockDim.x + threadIdx.x;
    if (n < N_NODES) {
        int lo = g_rowptr[n], hi = g_rowptr[n + 1];
        for (int i = lo + 1; i < hi; i++) {
            unsigned short key = g_col[i];
            int j = i - 1;
            while (j >= lo && g_col[j] > key) { g_col[j + 1] = g_col[j]; j--; }
            g_col[j + 1] = key;
        }
    }
}

// ---------------- main fused kernel: one CTA per batch ----------------
// SMEM: sx[4096*3] (x*c_src), sy[4096*3] (agg*c_dst), W1+b1, reduce buf.
// Phase A: thread-per-node CSR gather from SMEM (no atomics, no shuffles).
// Phase B: warp-per-node; lane L owns fixed output columns j=2L,2L+1 so the
//          W1 columns live in registers and the Wfc row read is a single
//          coalesced float2 per lane (256B contiguous per node).
__global__ __launch_bounds__(1024, 2)
void k_main(const float* __restrict__ x, const float* __restrict__ W1,
            const float* __restrict__ b1, const float* __restrict__ Wfc,
            const float* __restrict__ bfc, float* __restrict__ out)
{
    extern __shared__ float smem[];
    float*  sx  = smem;                       // 4096*3 floats
    float*  sy  = smem + N_NODES * 3;         // 4096*3 floats
    float4* sW1 = (float4*)(smem + N_NODES * 6);  // 64 float4: (W1row0,row1,row2,b1)
    float*  red = (float*)(sW1 + HID);        // 32 floats

    int tid = threadIdx.x;
    int b = blockIdx.x;

    if (tid < HID) {
        sW1[tid] = make_float4(W1[tid], W1[64 + tid], W1[128 + tid], b1[tid]);
    }

    // Stage x[b] * c_src into SMEM
    const float* xb = x + (size_t)b * (N_NODES * 3);
    for (int n = tid; n < N_NODES; n += 1024) {
        float c = g_csrc[n];
        sx[3 * n + 0] = xb[3 * n + 0] * c;
        sx[3 * n + 1] = xb[3 * n + 1] * c;
        sx[3 * n + 2] = xb[3 * n + 2] * c;
    }
    __syncthreads();

    // Phase A: per-node aggregation from SMEM via CSR (deterministic order)
    for (int n = tid; n < N_NODES; n += 1024) {
        int k0 = g_rowptr[n], k1 = g_rowptr[n + 1];
        float a0 = 0.f, a1 = 0.f, a2 = 0.f;
        for (int k = k0; k < k1; k++) {
            int s = (int)g_col[k];
            a0 += sx[3 * s + 0];
            a1 += sx[3 * s + 1];
            a2 += sx[3 * s + 2];
        }
        float cd = g_cdst[n];
        sy[3 * n + 0] = a0 * cd;
        sy[3 * n + 1] = a1 * cd;
        sy[3 * n + 2] = a2 * cd;
    }
    __syncthreads();

    // Phase B: h = relu(y @ W1 + b1); partial += h . Wfc[n]
    int w = tid >> 5, L = tid & 31;
    float4 wa = sW1[2 * L + 0];
    float4 wb = sW1[2 * L + 1];
    float partial = 0.f;
    for (int n = w; n < N_NODES; n += 32) {
        float y0 = sy[3 * n + 0], y1 = sy[3 * n + 1], y2 = sy[3 * n + 2];
        float h0 = fmaf(y2, wa.z, fmaf(y1, wa.y, fmaf(y0, wa.x, wa.w)));
        float h1 = fmaf(y2, wb.z, fmaf(y1, wb.y, fmaf(y0, wb.x, wb.w)));
        h0 = fmaxf(h0, 0.f);
        h1 = fmaxf(h1, 0.f);
        float2 wf = *(const float2*)(Wfc + (size_t)n * HID + 2 * L);
        partial = fmaf(h0, wf.x, partial);
        partial = fmaf(h1, wf.y, partial);
    }
    #pragma unroll
    for (int off = 16; off; off >>= 1)
        partial += __shfl_xor_sync(0xffffffffu, partial, off);
    if (L == 0) red[w] = partial;
    __syncthreads();
    if (tid < 32) {
        float v = red[tid];
        #pragma unroll
        for (int off = 16; off; off >>= 1)
            v += __shfl_xor_sync(0xffffffffu, v, off);
        if (tid == 0) out[b] = 1.0f / (1.0f + expf(-(v + bfc[0])));
    }
}

// ---------------- launch ----------------
extern "C" void kernel_launch(void* const* d_in, const int* in_sizes, int n_in,
                              void* d_out, int out_size) {
    const float* x   = (const float*)d_in[0];
    const float* W1  = (const float*)d_in[1];
    const float* b1  = (const float*)d_in[2];
    const float* Wfc = (const float*)d_in[3];
    const float* bfc = (const float*)d_in[4];
    const int*   src = (const int*)d_in[5];
    const int*   dst = (const int*)d_in[6];
    float* out = (float*)d_out;

    const int smem_bytes = (N_NODES * 6) * 4 + HID * 16 + 32 * 4;  // 99456
    cudaFuncSetAttribute(k_main, cudaFuncAttributeMaxDynamicSharedMemorySize, smem_bytes);

    k_zero<<<16, 256>>>();
    k_deg<<<N_EDGES / 256, 256>>>(src, dst);
    k_scan<<<1, 1024>>>();
    k_scatter<<<N_EDGES / 256, 256>>>(src, dst);
    k_sort<<<16, 256>>>();
    k_main<<<N_BATCH, 1024, smem_bytes>>>(x, W1, b1, Wfc, bfc, out);
}

// round 2
// speedup vs baseline: 1.1080x; 1.1080x over previous
#include <cuda_runtime.h>
#include <math.h>

#define N_NODES 4096
#define N_EDGES 65536
#define N_BATCH 256
#define HID 64
#define GB 2                      // batches per CTA

// ---------------- scratch (no allocations allowed) ----------------
__device__ int g_deg_in[N_NODES];
__device__ int g_deg_out[N_NODES];
__device__ int g_cursor[N_NODES];
__device__ int g_rowptr[N_NODES + 1];
__device__ unsigned short g_col[N_EDGES];
__device__ float g_csrc[N_NODES];
__device__ float g_cdst[N_NODES];

// ---------------- CSR construction ----------------
__global__ void k_zero() {
    int i = blockIdx.x * blockDim.x + threadIdx.x;
    if (i < N_NODES) { g_deg_in[i] = 0; g_deg_out[i] = 0; g_cursor[i] = 0; }
}

__global__ void k_deg(const int* __restrict__ src, const int* __restrict__ dst) {
    int e = blockIdx.x * blockDim.x + threadIdx.x;
    if (e < N_EDGES) {
        atomicAdd(&g_deg_out[src[e]], 1);
        atomicAdd(&g_deg_in[dst[e]], 1);
    }
}

__global__ void k_scan() {
    __shared__ int ssum[1024];
    int t = threadIdx.x;
    int d0 = g_deg_in[4 * t + 0];
    int d1 = g_deg_in[4 * t + 1];
    int d2 = g_deg_in[4 * t + 2];
    int d3 = g_deg_in[4 * t + 3];
    int s = d0 + d1 + d2 + d3;
    ssum[t] = s;
    __syncthreads();
    for (int off = 1; off < 1024; off <<= 1) {
        int v = (t >= off) ? ssum[t - off] : 0;
        __syncthreads();
        ssum[t] += v;
        __syncthreads();
    }
    int excl = ssum[t] - s;
    g_rowptr[4 * t + 0] = excl;
    g_rowptr[4 * t + 1] = excl + d0;
    g_rowptr[4 * t + 2] = excl + d0 + d1;
    g_rowptr[4 * t + 3] = excl + d0 + d1 + d2;
    if (t == 1023) g_rowptr[N_NODES] = ssum[1023];
    for (int n = t; n < N_NODES; n += 1024) {
        g_csrc[n] = rsqrtf(fmaxf((float)g_deg_out[n], 1.0f));
        g_cdst[n] = rsqrtf(fmaxf((float)g_deg_in[n], 1.0f));
    }
}

__global__ void k_scatter(const int* __restrict__ src, const int* __restrict__ dst) {
    int e = blockIdx.x * blockDim.x + threadIdx.x;
    if (e < N_EDGES) {
        int d = dst[e];
        int pos = atomicAdd(&g_cursor[d], 1);
        g_col[g_rowptr[d] + pos] = (unsigned short)src[e];
    }
}

// Sort each node's neighbor segment -> deterministic fp32 sum order
// independent of atomic scatter order, plus slightly better locality.
__global__ void k_sort() {
    int n = blockIdx.x * blockDim.x + threadIdx.x;
    if (n < N_NODES) {
        int lo = g_rowptr[n], hi = g_rowptr[n + 1];
        for (int i = lo + 1; i < hi; i++) {
            unsigned short key = g_col[i];
            int j = i - 1;
            while (j >= lo && g_col[j] > key) { g_col[j + 1] = g_col[j]; j--; }
            g_col[j + 1] = key;
        }
    }
}

// ---------------- main fused kernel: one CTA per 2 batches ----------------
// SMEM: sxA/sxB as float4-padded node features (single LDS.128 per gather),
//       syA/syB packed 3-float aggregates, W1+b1, reduce buffers.
// Phase A: thread-per-node CSR gather (no atomics, no shuffles); one LDS.128
//          per (edge, batch).
// Phase B: warp-per-node; lane L owns columns 2L,2L+1; Wfc row read is one
//          coalesced 256B float2 transaction serving BOTH batches.
__global__ __launch_bounds__(1024, 1)
void k_main(const float* __restrict__ x, const float* __restrict__ W1,
            const float* __restrict__ b1, const float* __restrict__ Wfc,
            const float* __restrict__ bfc, float* __restrict__ out)
{
    extern __shared__ float smem[];
    float4* sxA = (float4*)smem;                     // 4096 float4 = 64KB
    float4* sxB = sxA + N_NODES;                     // 64KB
    float*  syA = (float*)(sxB + N_NODES);           // 4096*3 floats = 48KB
    float*  syB = syA + N_NODES * 3;                 // 48KB
    float4* sW1 = (float4*)(syB + N_NODES * 3);      // 64 float4
    float*  red = (float*)(sW1 + HID);               // 64 floats (2x32)

    int tid = threadIdx.x;
    int b0 = blockIdx.x * GB;
    int b1i = b0 + 1;

    if (tid < HID) {
        sW1[tid] = make_float4(W1[tid], W1[64 + tid], W1[128 + tid], b1[tid]);
    }

    // Stage x[b]*c_src into SMEM (float4-padded)
    const float* xa = x + (size_t)b0 * (N_NODES * 3);
    const float* xb = x + (size_t)b1i * (N_NODES * 3);
    for (int n = tid; n < N_NODES; n += 1024) {
        float c = g_csrc[n];
        sxA[n] = make_float4(xa[3 * n] * c, xa[3 * n + 1] * c, xa[3 * n + 2] * c, 0.f);
        sxB[n] = make_float4(xb[3 * n] * c, xb[3 * n + 1] * c, xb[3 * n + 2] * c, 0.f);
    }
    __syncthreads();

    // Phase A: per-node aggregation from SMEM via CSR (deterministic order)
    for (int n = tid; n < N_NODES; n += 1024) {
        int k0 = g_rowptr[n], k1 = g_rowptr[n + 1];
        float a0 = 0.f, a1 = 0.f, a2 = 0.f;
        float c0 = 0.f, c1 = 0.f, c2 = 0.f;
        for (int k = k0; k < k1; k++) {
            int s = (int)g_col[k];
            float4 va = sxA[s];
            float4 vb = sxB[s];
            a0 += va.x; a1 += va.y; a2 += va.z;
            c0 += vb.x; c1 += vb.y; c2 += vb.z;
        }
        float cd = g_cdst[n];
        syA[3 * n + 0] = a0 * cd; syA[3 * n + 1] = a1 * cd; syA[3 * n + 2] = a2 * cd;
        syB[3 * n + 0] = c0 * cd; syB[3 * n + 1] = c1 * cd; syB[3 * n + 2] = c2 * cd;
    }
    __syncthreads();

    // Phase B: h = relu(y @ W1 + b1); partial += h . Wfc[n] for both batches
    int w = tid >> 5, L = tid & 31;
    float4 wa = sW1[2 * L + 0];
    float4 wb = sW1[2 * L + 1];
    float pA = 0.f, pB = 0.f;
    for (int n = w; n < N_NODES; n += 32) {
        float2 wf = *(const float2*)(Wfc + (size_t)n * HID + 2 * L);

        float y0 = syA[3 * n + 0], y1 = syA[3 * n + 1], y2 = syA[3 * n + 2];
        float h0 = fmaf(y2, wa.z, fmaf(y1, wa.y, fmaf(y0, wa.x, wa.w)));
        float h1 = fmaf(y2, wb.z, fmaf(y1, wb.y, fmaf(y0, wb.x, wb.w)));
        pA = fmaf(fmaxf(h0, 0.f), wf.x, pA);
        pA = fmaf(fmaxf(h1, 0.f), wf.y, pA);

        y0 = syB[3 * n + 0]; y1 = syB[3 * n + 1]; y2 = syB[3 * n + 2];
        h0 = fmaf(y2, wa.z, fmaf(y1, wa.y, fmaf(y0, wa.x, wa.w)));
        h1 = fmaf(y2, wb.z, fmaf(y1, wb.y, fmaf(y0, wb.x, wb.w)));
        pB = fmaf(fmaxf(h0, 0.f), wf.x, pB);
        pB = fmaf(fmaxf(h1, 0.f), wf.y, pB);
    }
    #pragma unroll
    for (int off = 16; off; off >>= 1) {
        pA += __shfl_xor_sync(0xffffffffu, pA, off);
        pB += __shfl_xor_sync(0xffffffffu, pB, off);
    }
    if (L == 0) { red[w] = pA; red[32 + w] = pB; }
    __syncthreads();
    if (tid < 32) {
        float vA = red[tid];
        float vB = red[32 + tid];
        #pragma unroll
        for (int off = 16; off; off >>= 1) {
            vA += __shfl_xor_sync(0xffffffffu, vA, off);
            vB += __shfl_xor_sync(0xffffffffu, vB, off);
        }
        if (tid == 0) {
            float bias = bfc[0];
            out[b0]  = 1.0f / (1.0f + expf(-(vA + bias)));
            out[b1i] = 1.0f / (1.0f + expf(-(vB + bias)));
        }
    }
}

// ---------------- launch ----------------
extern "C" void kernel_launch(void* const* d_in, const int* in_sizes, int n_in,
                              void* d_out, int out_size) {
    const float* x   = (const float*)d_in[0];
    const float* W1  = (const float*)d_in[1];
    const float* b1  = (const float*)d_in[2];
    const float* Wfc = (const float*)d_in[3];
    const float* bfc = (const float*)d_in[4];
    const int*   src = (const int*)d_in[5];
    const int*   dst = (const int*)d_in[6];
    float* out = (float*)d_out;

    // 64KB*2 (sx) + 48KB*2 (sy) + W1/b1 + reduce
    const int smem_bytes = N_NODES * 16 * 2 + N_NODES * 12 * 2 + HID * 16 + 64 * 4;
    cudaFuncSetAttribute(k_main, cudaFuncAttributeMaxDynamicSharedMemorySize, smem_bytes);

    k_zero<<<16, 256>>>();
    k_deg<<<N_EDGES / 256, 256>>>(src, dst);
    k_scan<<<1, 1024>>>();
    k_scatter<<<N_EDGES / 128, 128>>>(src, dst);
    k_sort<<<16, 256>>>();
    k_main<<<N_BATCH / GB, 1024, smem_bytes>>>(x, W1, b1, Wfc, bfc, out);
}

// round 4
// speedup vs baseline: 2.0741x; 1.8718x over previous
#include <cuda_runtime.h>
#include <math.h>
#include <stdint.h>

#define N_NODES 4096
#define N_EDGES 65536
#define N_BATCH 256
#define HID 64
#define GB 2                       // batches per CTA
#define DEG_CTAS 16
#define FPSCALE 2097152.0f         // 2^21 fixed-point scale

// ---------------- scratch (no device allocations allowed) ----------------
__device__ int g_part_in[DEG_CTAS * N_NODES];
__device__ int g_part_out[DEG_CTAS * N_NODES];
__device__ int g_rowptr[N_NODES + 1];
__device__ int g_cursor[N_NODES];
__device__ unsigned short g_col[N_EDGES];
__device__ float g_csrcs[N_NODES];   // rsqrt(deg_out) * 2^21  (staging scale)
__device__ float g_cdsts[N_NODES];   // rsqrt(deg_in)  * 2^-21 (unscale)

// packed f32x2 helpers
#define FMA_F32X2(out, a, b, c) \
    asm("fma.rn.f32x2 %0, %1, %2, %3;" : "=l"(out) : "l"(a), "l"(b), "l"(c))
__device__ __forceinline__ unsigned long long packf2(float lo, float hi) {
    unsigned long long r;
    asm("mov.b64 %0, {%1, %2};" : "=l"(r) : "f"(lo), "f"(hi));
    return r;
}
__device__ __forceinline__ void unpackf2(unsigned long long v, float& lo, float& hi) {
    asm("mov.b64 {%0, %1}, %2;" : "=f"(lo), "=f"(hi) : "l"(v));
}

// -------- launch 0: per-CTA smem histogram of in/out degrees --------
__global__ __launch_bounds__(1024) void k_deg(const int* __restrict__ src,
                                              const int* __restrict__ dst) {
    __shared__ int sh_in[N_NODES];
    __shared__ int sh_out[N_NODES];
    int tid = threadIdx.x, cta = blockIdx.x;
    for (int i = tid; i < N_NODES; i += 1024) { sh_in[i] = 0; sh_out[i] = 0; }
    __syncthreads();
    int e0 = cta * (N_EDGES / DEG_CTAS);
    for (int i = tid; i < N_EDGES / DEG_CTAS; i += 1024) {
        atomicAdd(&sh_out[src[e0 + i]], 1);
        atomicAdd(&sh_in[dst[e0 + i]], 1);
    }
    __syncthreads();
    for (int i = tid; i < N_NODES; i += 1024) {
        g_part_in[cta * N_NODES + i] = sh_in[i];
        g_part_out[cta * N_NODES + i] = sh_out[i];
    }
}

// -------- launch 1: reduce partials, scan rowptr, norms, zero cursor --------
__global__ __launch_bounds__(1024) void k_scan() {
    __shared__ int ssum[1024];
    int t = threadIdx.x;
    int din[4], dout[4];
    #pragma unroll
    for (int j = 0; j < 4; j++) { din[j] = 0; dout[j] = 0; }
    #pragma unroll
    for (int c = 0; c < DEG_CTAS; c++) {
        #pragma unroll
        for (int j = 0; j < 4; j++) {
            din[j]  += g_part_in[c * N_NODES + 4 * t + j];
            dout[j] += g_part_out[c * N_NODES + 4 * t + j];
        }
    }
    int s = din[0] + din[1] + din[2] + din[3];
    ssum[t] = s;
    __syncthreads();
    for (int off = 1; off < 1024; off <<= 1) {
        int v = (t >= off) ? ssum[t - off] : 0;
        __syncthreads();
        ssum[t] += v;
        __syncthreads();
    }
    int excl = ssum[t] - s;
    g_rowptr[4 * t + 0] = excl;
    g_rowptr[4 * t + 1] = excl + din[0];
    g_rowptr[4 * t + 2] = excl + din[0] + din[1];
    g_rowptr[4 * t + 3] = excl + din[0] + din[1] + din[2];
    if (t == 1023) g_rowptr[N_NODES] = ssum[1023];
    #pragma unroll
    for (int j = 0; j < 4; j++) {
        int n = 4 * t + j;
        g_csrcs[n] = rsqrtf(fmaxf((float)dout[j], 1.0f)) * FPSCALE;
        g_cdsts[n] = rsqrtf(fmaxf((float)din[j], 1.0f)) * (1.0f / FPSCALE);
        g_cursor[n] = 0;
    }
}

// -------- launch 2: scatter edges into CSR (order-free: sums are integer) --------
__global__ __launch_bounds__(1024) void k_scatter(const int* __restrict__ src,
                                                  const int* __restrict__ dst) {
    int e = blockIdx.x * 1024 + threadIdx.x;
    if (e < N_EDGES) {
        int d = dst[e];
        int pos = atomicAdd(&g_cursor[d], 1);
        g_col[g_rowptr[d] + pos] = (unsigned short)src[e];
    }
}

// -------- launch 3: fused main, one CTA per 2 batches --------
// SMEM: sxp[c][n] = int2(fixA, fixB) fixed-point scaled source features,
//       syp[c][n] = float2(yA, yB) aggregated+normalized,
// Phase A: thread-per-node CSR gather, 3 LDS.64 + 6 IADD per edge; integer
//          accumulation => bitwise-deterministic regardless of g_col order.
// Phase B: warp-per-node, lane L owns cols 2L/2L+1; y loaded as packed
//          f32x2 pair straight from SMEM; 6 FFMA2 + 4 FMNMX + 4 FFMA per node.
__global__ __launch_bounds__(1024, 1)
void k_main(const float* __restrict__ x, const float* __restrict__ W1,
            const float* __restrict__ b1, const float* __restrict__ Wfc,
            const float* __restrict__ bfc, float* __restrict__ out)
{
    extern __shared__ int smem[];
    int2* sxp0 = (int2*)smem;                 // 32KB
    int2* sxp1 = sxp0 + N_NODES;              // 32KB
    int2* sxp2 = sxp1 + N_NODES;              // 32KB
    unsigned long long* syp0 = (unsigned long long*)(sxp2 + N_NODES);  // 32KB
    unsigned long long* syp1 = syp0 + N_NODES;
    unsigned long long* syp2 = syp1 + N_NODES;
    float* red = (float*)(syp2 + N_NODES);    // 64 floats

    int tid = threadIdx.x;
    int b0 = blockIdx.x * GB;

    // ---- stage x * csrc (fixed-point) into SMEM, both batches packed ----
    const float* xa = x + (size_t)b0 * (N_NODES * 3);
    const float* xb = xa + (size_t)(N_NODES * 3);
    for (int i = tid; i < N_NODES * 3; i += 1024) {
        int n = i / 3, c = i - 3 * n;
        float sc = g_csrcs[n];
        int vA = __float2int_rn(xa[i] * sc);
        int vB = __float2int_rn(xb[i] * sc);
        int2 v = make_int2(vA, vB);
        if (c == 0) sxp0[n] = v; else if (c == 1) sxp1[n] = v; else sxp2[n] = v;
    }
    __syncthreads();

    // ---- phase A: CSR gather with integer accumulation ----
    for (int n = tid; n < N_NODES; n += 1024) {
        int k0 = g_rowptr[n], k1 = g_rowptr[n + 1];
        int a0 = 0, a1 = 0, a2 = 0, c0 = 0, c1 = 0, c2 = 0;
        #pragma unroll 4
        for (int k = k0; k < k1; k++) {
            int s = (int)__ldg(&g_col[k]);
            int2 v0 = sxp0[s], v1 = sxp1[s], v2 = sxp2[s];
            a0 += v0.x; c0 += v0.y;
            a1 += v1.x; c1 += v1.y;
            a2 += v2.x; c2 += v2.y;
        }
        float cd = g_cdsts[n];
        syp0[n] = packf2((float)a0 * cd, (float)c0 * cd);
        syp1[n] = packf2((float)a1 * cd, (float)c1 * cd);
        syp2[n] = packf2((float)a2 * cd, (float)c2 * cd);
    }
    __syncthreads();

    // ---- phase B: h = relu(y @ W1 + b1); accumulate h . Wfc ----
    int w = tid >> 5, L = tid & 31;
    int j0 = 2 * L, j1 = 2 * L + 1;
    unsigned long long w00 = packf2(W1[j0],       W1[j0]);        // row0 col j0
    unsigned long long w10 = packf2(W1[64 + j0],  W1[64 + j0]);
    unsigned long long w20 = packf2(W1[128 + j0], W1[128 + j0]);
    unsigned long long bb0 = packf2(b1[j0],       b1[j0]);
    unsigned long long w01 = packf2(W1[j1],       W1[j1]);
    unsigned long long w11 = packf2(W1[64 + j1],  W1[64 + j1]);
    unsigned long long w21 = packf2(W1[128 + j1], W1[128 + j1]);
    unsigned long long bb1 = packf2(b1[j1],       b1[j1]);

    float pA = 0.f, pB = 0.f;
    const float2* wfp = (const float2*)(Wfc + 2 * L);
    #pragma unroll 2
    for (int n = w; n < N_NODES; n += 32) {
        unsigned long long y0 = syp0[n];
        unsigned long long y1 = syp1[n];
        unsigned long long y2 = syp2[n];
        float2 wf = wfp[(size_t)n * 32];

        unsigned long long h0, h1;
        FMA_F32X2(h0, y0, w00, bb0);
        FMA_F32X2(h0, y1, w10, h0);
        FMA_F32X2(h0, y2, w20, h0);
        FMA_F32X2(h1, y0, w01, bb1);
        FMA_F32X2(h1, y1, w11, h1);
        FMA_F32X2(h1, y2, w21, h1);

        float hA0, hB0, hA1, hB1;
        unpackf2(h0, hA0, hB0);
        unpackf2(h1, hA1, hB1);
        hA0 = fmaxf(hA0, 0.f); hB0 = fmaxf(hB0, 0.f);
        hA1 = fmaxf(hA1, 0.f); hB1 = fmaxf(hB1, 0.f);

        pA = fmaf(hA0, wf.x, pA);
        pA = fmaf(hA1, wf.y, pA);
        pB = fmaf(hB0, wf.x, pB);
        pB = fmaf(hB1, wf.y, pB);
    }
    #pragma unroll
    for (int off = 16; off; off >>= 1) {
        pA += __shfl_xor_sync(0xffffffffu, pA, off);
        pB += __shfl_xor_sync(0xffffffffu, pB, off);
    }
    if (L == 0) { red[w] = pA; red[32 + w] = pB; }
    __syncthreads();
    if (tid < 32) {
        float vA = red[tid];
        float vB = red[32 + tid];
        #pragma unroll
        for (int off = 16; off; off >>= 1) {
            vA += __shfl_xor_sync(0xffffffffu, vA, off);
            vB += __shfl_xor_sync(0xffffffffu, vB, off);
        }
        if (tid == 0) {
            float bias = bfc[0];
            out[b0]     = 1.0f / (1.0f + expf(-(vA + bias)));
            out[b0 + 1] = 1.0f / (1.0f + expf(-(vB + bias)));
        }
    }
}

// ---------------- launch ----------------
extern "C" void kernel_launch(void* const* d_in, const int* in_sizes, int n_in,
                              void* d_out, int out_size) {
    const float* x   = (const float*)d_in[0];
    const float* W1  = (const float*)d_in[1];
    const float* b1  = (const float*)d_in[2];
    const float* Wfc = (const float*)d_in[3];
    const float* bfc = (const float*)d_in[4];
    const int*   src = (const int*)d_in[5];
    const int*   dst = (const int*)d_in[6];
    float* out = (float*)d_out;

    const int smem_bytes = N_NODES * 8 * 3      // sxp (int2 x3)
                         + N_NODES * 8 * 3      // syp (f32x2 x3)
                         + 64 * 4;              // red
    cudaFuncSetAttribute(k_main, cudaFuncAttributeMaxDynamicSharedMemorySize, smem_bytes);

    k_deg<<<DEG_CTAS, 1024>>>(src, dst);
    k_scan<<<1, 1024>>>();
    k_scatter<<<N_EDGES / 1024, 1024>>>(src, dst);
    k_main<<<N_BATCH / GB, 1024, smem_bytes>>>(x, W1, b1, Wfc, bfc, out);
}

// round 6
// speedup vs baseline: 2.4984x; 1.2046x over previous
#include <cuda_runtime.h>
#include <math.h>
#include <stdint.h>

#define N_NODES 4096
#define N_EDGES 65536
#define N_BATCH 256
#define HID 64
#define GB 2                       // batches per CTA
#define DEG_CTAS 16
#define FPSCALE 4096.0f            // 2^12 fixed-point scale (s16 range)

// ---------------- scratch (no device allocations allowed) ----------------
__device__ int g_part_in[DEG_CTAS * N_NODES];
__device__ int g_part_out[DEG_CTAS * N_NODES];
__device__ int g_rowptr[N_NODES + 1];
__device__ int g_cursor[N_NODES];
__device__ unsigned short g_col[N_EDGES];
__device__ float g_csrcs[N_NODES];   // rsqrt(deg_out) * 2^12  (staging scale)
__device__ float g_cdsts[N_NODES];   // rsqrt(deg_in)  * 2^-12 (unscale)

// packed f32x2 helpers
#define FMA_F32X2(out, a, b, c) \
    asm("fma.rn.f32x2 %0, %1, %2, %3;" : "=l"(out) : "l"(a), "l"(b), "l"(c))
__device__ __forceinline__ unsigned long long packf2(float lo, float hi) {
    unsigned long long r;
    asm("mov.b64 %0, {%1, %2};" : "=l"(r) : "f"(lo), "f"(hi));
    return r;
}
__device__ __forceinline__ void unpackf2(unsigned long long v, float& lo, float& hi) {
    asm("mov.b64 {%0, %1}, %2;" : "=f"(lo), "=f"(hi) : "l"(v));
}

__device__ __forceinline__ int q16(float v) {
    int f = __float2int_rn(v);
    f = max(-32768, min(32767, f));
    return f;
}

// -------- launch 0: per-CTA smem histogram of in/out degrees --------
__global__ __launch_bounds__(1024) void k_deg(const int* __restrict__ src,
                                              const int* __restrict__ dst) {
    __shared__ int sh_in[N_NODES];
    __shared__ int sh_out[N_NODES];
    int tid = threadIdx.x, cta = blockIdx.x;
    for (int i = tid; i < N_NODES; i += 1024) { sh_in[i] = 0; sh_out[i] = 0; }
    __syncthreads();
    int e0 = cta * (N_EDGES / DEG_CTAS);
    for (int i = tid; i < N_EDGES / DEG_CTAS; i += 1024) {
        atomicAdd(&sh_out[src[e0 + i]], 1);
        atomicAdd(&sh_in[dst[e0 + i]], 1);
    }
    __syncthreads();
    for (int i = tid; i < N_NODES; i += 1024) {
        g_part_in[cta * N_NODES + i] = sh_in[i];
        g_part_out[cta * N_NODES + i] = sh_out[i];
    }
}

// -------- launch 1: reduce partials, scan rowptr, norms, zero cursor --------
__global__ __launch_bounds__(1024) void k_scan() {
    __shared__ int ssum[1024];
    int t = threadIdx.x;
    int din[4], dout[4];
    #pragma unroll
    for (int j = 0; j < 4; j++) { din[j] = 0; dout[j] = 0; }
    #pragma unroll
    for (int c = 0; c < DEG_CTAS; c++) {
        #pragma unroll
        for (int j = 0; j < 4; j++) {
            din[j]  += g_part_in[c * N_NODES + 4 * t + j];
            dout[j] += g_part_out[c * N_NODES + 4 * t + j];
        }
    }
    int s = din[0] + din[1] + din[2] + din[3];
    ssum[t] = s;
    __syncthreads();
    for (int off = 1; off < 1024; off <<= 1) {
        int v = (t >= off) ? ssum[t - off] : 0;
        __syncthreads();
        ssum[t] += v;
        __syncthreads();
    }
    int excl = ssum[t] - s;
    g_rowptr[4 * t + 0] = excl;
    g_rowptr[4 * t + 1] = excl + din[0];
    g_rowptr[4 * t + 2] = excl + din[0] + din[1];
    g_rowptr[4 * t + 3] = excl + din[0] + din[1] + din[2];
    if (t == 1023) g_rowptr[N_NODES] = ssum[1023];
    #pragma unroll
    for (int j = 0; j < 4; j++) {
        int n = 4 * t + j;
        g_csrcs[n] = rsqrtf(fmaxf((float)dout[j], 1.0f)) * FPSCALE;
        g_cdsts[n] = rsqrtf(fmaxf((float)din[j], 1.0f)) * (1.0f / FPSCALE);
        g_cursor[n] = 0;
    }
}

// -------- launch 2: scatter edges into CSR (order-free: sums are integer) --------
__global__ __launch_bounds__(1024) void k_scatter(const int* __restrict__ src,
                                                  const int* __restrict__ dst) {
    int e = blockIdx.x * 1024 + threadIdx.x;
    if (e < N_EDGES) {
        int d = dst[e];
        int pos = atomicAdd(&g_cursor[d], 1);
        g_col[g_rowptr[d] + pos] = (unsigned short)src[e];
    }
}

// -------- launch 3: fused main, one CTA per 2 batches --------
// SMEM: sq01[n] = int2{ pack16(f0A,f1A), pack16(f0B,f1B) }, sq2[n] = pack16(f2A,f2B)
//       (s16 fixed-point scale 2^12) -> 12 bytes/edge through the crossbar,
//       syp[c][n] = float2(yA, yB) aggregated+normalized.
// Phase A: thread-per-node CSR gather, LDS.64 + LDS.32 + 12 ALU per edge;
//          int32 accumulation => bitwise-deterministic.
// Phase B: warp-per-node, lane L owns cols 2L/2L+1; packed f32x2 math.
__global__ __launch_bounds__(1024, 1)
void k_main(const float* __restrict__ x, const float* __restrict__ W1,
            const float* __restrict__ b1, const float* __restrict__ Wfc,
            const float* __restrict__ bfc, float* __restrict__ out)
{
    extern __shared__ int smem[];
    int2* sq01 = (int2*)smem;                         // 32KB
    int*  sq2  = (int*)(sq01 + N_NODES);              // 16KB
    unsigned long long* syp0 = (unsigned long long*)(sq2 + N_NODES);  // 32KB
    unsigned long long* syp1 = syp0 + N_NODES;        // 32KB
    unsigned long long* syp2 = syp1 + N_NODES;        // 32KB
    float* red = (float*)(syp2 + N_NODES);            // 64 floats

    int tid = threadIdx.x;
    int b0 = blockIdx.x * GB;

    // ---- stage x * csrc (s16 fixed-point) into SMEM, both batches packed ----
    const float* xa = x + (size_t)b0 * (N_NODES * 3);
    const float* xb = xa + (size_t)(N_NODES * 3);
    for (int n = tid; n < N_NODES; n += 1024) {
        float sc = g_csrcs[n];
        int f0A = q16(xa[3 * n + 0] * sc);
        int f1A = q16(xa[3 * n + 1] * sc);
        int f2A = q16(xa[3 * n + 2] * sc);
        int f0B = q16(xb[3 * n + 0] * sc);
        int f1B = q16(xb[3 * n + 1] * sc);
        int f2B = q16(xb[3 * n + 2] * sc);
        sq01[n] = make_int2((f0A & 0xFFFF) | (f1A << 16),
                            (f0B & 0xFFFF) | (f1B << 16));
        sq2[n]  = (f2A & 0xFFFF) | (f2B << 16);
    }
    __syncthreads();

    // ---- phase A: CSR gather with int32 accumulation ----
    for (int n = tid; n < N_NODES; n += 1024) {
        int k0 = g_rowptr[n], k1 = g_rowptr[n + 1];
        int a0A = 0, a1A = 0, a2A = 0, a0B = 0, a1B = 0, a2B = 0;
        #pragma unroll 4
        for (int k = k0; k < k1; k++) {
            int s = (int)__ldg(&g_col[k]);
            int2 v01 = sq01[s];
            int  v2  = sq2[s];
            a0A += (int)(short)v01.x;  a1A += (v01.x >> 16);
            a0B += (int)(short)v01.y;  a1B += (v01.y >> 16);
            a2A += (int)(short)v2;     a2B += (v2 >> 16);
        }
        float cd = g_cdsts[n];
        syp0[n] = packf2((float)a0A * cd, (float)a0B * cd);
        syp1[n] = packf2((float)a1A * cd, (float)a1B * cd);
        syp2[n] = packf2((float)a2A * cd, (float)a2B * cd);
    }
    __syncthreads();

    // ---- phase B: h = relu(y @ W1 + b1); accumulate h . Wfc ----
    int w = tid >> 5, L = tid & 31;
    int j0 = 2 * L, j1 = 2 * L + 1;
    unsigned long long w00 = packf2(W1[j0],       W1[j0]);
    unsigned long long w10 = packf2(W1[64 + j0],  W1[64 + j0]);
    unsigned long long w20 = packf2(W1[128 + j0], W1[128 + j0]);
    unsigned long long bb0 = packf2(b1[j0],       b1[j0]);
    unsigned long long w01 = packf2(W1[j1],       W1[j1]);
    unsigned long long w11 = packf2(W1[64 + j1],  W1[64 + j1]);
    unsigned long long w21 = packf2(W1[128 + j1], W1[128 + j1]);
    unsigned long long bb1 = packf2(b1[j1],       b1[j1]);

    float pA = 0.f, pB = 0.f;
    const float2* wfp = (const float2*)(Wfc + 2 * L);
    #pragma unroll 2
    for (int n = w; n < N_NODES; n += 32) {
        unsigned long long y0 = syp0[n];
        unsigned long long y1 = syp1[n];
        unsigned long long y2 = syp2[n];
        float2 wf = wfp[(size_t)n * 32];

        unsigned long long h0, h1;
        FMA_F32X2(h0, y0, w00, bb0);
        FMA_F32X2(h0, y1, w10, h0);
        FMA_F32X2(h0, y2, w20, h0);
        FMA_F32X2(h1, y0, w01, bb1);
        FMA_F32X2(h1, y1, w11, h1);
        FMA_F32X2(h1, y2, w21, h1);

        float hA0, hB0, hA1, hB1;
        unpackf2(h0, hA0, hB0);
        unpackf2(h1, hA1, hB1);
        hA0 = fmaxf(hA0, 0.f); hB0 = fmaxf(hB0, 0.f);
        hA1 = fmaxf(hA1, 0.f); hB1 = fmaxf(hB1, 0.f);

        pA = fmaf(hA0, wf.x, pA);
        pA = fmaf(hA1, wf.y, pA);
        pB = fmaf(hB0, wf.x, pB);
        pB = fmaf(hB1, wf.y, pB);
    }
    #pragma unroll
    for (int off = 16; off; off >>= 1) {
        pA += __shfl_xor_sync(0xffffffffu, pA, off);
        pB += __shfl_xor_sync(0xffffffffu, pB, off);
    }
    if (L == 0) { red[w] = pA; red[32 + w] = pB; }
    __syncthreads();
    if (tid < 32) {
        float vA = red[tid];
        float vB = red[32 + tid];
        #pragma unroll
        for (int off = 16; off; off >>= 1) {
            vA += __shfl_xor_sync(0xffffffffu, vA, off);
            vB += __shfl_xor_sync(0xffffffffu, vB, off);
        }
        if (tid == 0) {
            float bias = bfc[0];
            out[b0]     = 1.0f / (1.0f + expf(-(vA + bias)));
            out[b0 + 1] = 1.0f / (1.0f + expf(-(vB + bias)));
        }
    }
}

// ---------------- launch ----------------
extern "C" void kernel_launch(void* const* d_in, const int* in_sizes, int n_in,
                              void* d_out, int out_size) {
    const float* x   = (const float*)d_in[0];
    const float* W1  = (const float*)d_in[1];
    const float* b1  = (const float*)d_in[2];
    const float* Wfc = (const float*)d_in[3];
    const float* bfc = (const float*)d_in[4];
    const int*   src = (const int*)d_in[5];
    const int*   dst = (const int*)d_in[6];
    float* out = (float*)d_out;

    const int smem_bytes = N_NODES * 8        // sq01
                         + N_NODES * 4        // sq2
                         + N_NODES * 8 * 3    // syp (f32x2 x3)
                         + 64 * 4;            // red
    cudaFuncSetAttribute(k_main, cudaFuncAttributeMaxDynamicSharedMemorySize, smem_bytes);

    k_deg<<<DEG_CTAS, 1024>>>(src, dst);
    k_scan<<<1, 1024>>>();
    k_scatter<<<N_EDGES / 1024, 1024>>>(src, dst);
    k_main<<<N_BATCH / GB, 1024, smem_bytes>>>(x, W1, b1, Wfc, bfc, out);
}

// round 7
// speedup vs baseline: 2.5011x; 1.0011x over previous
#include <cuda_runtime.h>
#include <math.h>
#include <stdint.h>

#define N_NODES 4096
#define N_EDGES 65536
#define N_BATCH 256
#define DEG_CTAS 16
#define FPSCALE 4096.0f            // 2^12 fixed-point scale (s16 range)
#define NCHUNKS 128                // node chunks of 32
#define GPAIRS 4                   // 4 group-pairs x 64 batches = 256

// ---------------- scratch (no device allocations allowed) ----------------
__device__ int g_part_in[DEG_CTAS * N_NODES];
__device__ int g_part_out[DEG_CTAS * N_NODES];
__device__ int g_rowptr[N_NODES + 1];
__device__ int g_cursor[N_NODES];
__device__ unsigned short g_col[N_EDGES];
__device__ float g_csrcs[N_NODES];   // rsqrt(deg_out) * 2^12
__device__ float g_cdsts[N_NODES];   // rsqrt(deg_in)  * 2^-12
__device__ unsigned long long g_xqT[(size_t)N_NODES * N_BATCH];  // [node][batch] 3x s16
__device__ float g_partial[N_BATCH * NCHUNKS];

// packed f32x2 helpers
#define FMA_F32X2(out, a, b, c) \
    asm("fma.rn.f32x2 %0, %1, %2, %3;" : "=l"(out) : "l"(a), "l"(b), "l"(c))
__device__ __forceinline__ unsigned long long packf2(float lo, float hi) {
    unsigned long long r;
    asm("mov.b64 %0, {%1, %2};" : "=l"(r) : "f"(lo), "f"(hi));
    return r;
}
__device__ __forceinline__ void unpackf2(unsigned long long v, float& lo, float& hi) {
    asm("mov.b64 {%0, %1}, %2;" : "=f"(lo), "=f"(hi) : "l"(v));
}
__device__ __forceinline__ int q16(float v) {
    int f = __float2int_rn(v);
    f = max(-32768, min(32767, f));
    return f;
}

// -------- launch 0: per-CTA smem histogram of in/out degrees --------
__global__ __launch_bounds__(1024) void k_deg(const int* __restrict__ src,
                                              const int* __restrict__ dst) {
    __shared__ int sh_in[N_NODES];
    __shared__ int sh_out[N_NODES];
    int tid = threadIdx.x, cta = blockIdx.x;
    for (int i = tid; i < N_NODES; i += 1024) { sh_in[i] = 0; sh_out[i] = 0; }
    __syncthreads();
    int e0 = cta * (N_EDGES / DEG_CTAS);
    for (int i = tid; i < N_EDGES / DEG_CTAS; i += 1024) {
        atomicAdd(&sh_out[src[e0 + i]], 1);
        atomicAdd(&sh_in[dst[e0 + i]], 1);
    }
    __syncthreads();
    for (int i = tid; i < N_NODES; i += 1024) {
        g_part_in[cta * N_NODES + i] = sh_in[i];
        g_part_out[cta * N_NODES + i] = sh_out[i];
    }
}

// -------- launch 1: reduce partials, scan rowptr, norms, zero cursor --------
__global__ __launch_bounds__(1024) void k_scan() {
    __shared__ int ssum[1024];
    int t = threadIdx.x;
    int din[4], dout[4];
    #pragma unroll
    for (int j = 0; j < 4; j++) { din[j] = 0; dout[j] = 0; }
    #pragma unroll
    for (int c = 0; c < DEG_CTAS; c++) {
        #pragma unroll
        for (int j = 0; j < 4; j++) {
            din[j]  += g_part_in[c * N_NODES + 4 * t + j];
            dout[j] += g_part_out[c * N_NODES + 4 * t + j];
        }
    }
    int s = din[0] + din[1] + din[2] + din[3];
    ssum[t] = s;
    __syncthreads();
    for (int off = 1; off < 1024; off <<= 1) {
        int v = (t >= off) ? ssum[t - off] : 0;
        __syncthreads();
        ssum[t] += v;
        __syncthreads();
    }
    int excl = ssum[t] - s;
    g_rowptr[4 * t + 0] = excl;
    g_rowptr[4 * t + 1] = excl + din[0];
    g_rowptr[4 * t + 2] = excl + din[0] + din[1];
    g_rowptr[4 * t + 3] = excl + din[0] + din[1] + din[2];
    if (t == 1023) g_rowptr[N_NODES] = ssum[1023];
    #pragma unroll
    for (int j = 0; j < 4; j++) {
        int n = 4 * t + j;
        g_csrcs[n] = rsqrtf(fmaxf((float)dout[j], 1.0f)) * FPSCALE;
        g_cdsts[n] = rsqrtf(fmaxf((float)din[j], 1.0f)) * (1.0f / FPSCALE);
        g_cursor[n] = 0;
    }
}

// -------- launch 2: scatter edges into CSR (order-free: sums are integer) --------
__global__ __launch_bounds__(1024) void k_scatter(const int* __restrict__ src,
                                                  const int* __restrict__ dst) {
    int e = blockIdx.x * 1024 + threadIdx.x;
    if (e < N_EDGES) {
        int d = dst[e];
        int pos = atomicAdd(&g_cursor[d], 1);
        g_col[g_rowptr[d] + pos] = (unsigned short)src[e];
    }
}

// -------- launch 3: transpose+quantize x into [node][batch] u64 (3x s16) --------
// CTA = (64-node tile, 64-batch tile). Reads coalesced per-batch rows via SMEM,
// writes batch-contiguous 512B runs.
__global__ __launch_bounds__(256) void k_stage(const float* __restrict__ x) {
    extern __shared__ float sx[];   // [64][193] padded
    int n0 = (blockIdx.x >> 2) * 64;
    int b0 = (blockIdx.x & 3) * 64;
    int tid = threadIdx.x;
    for (int i = tid; i < 64 * 192; i += 256) {
        int bl = i / 192, c = i - bl * 192;
        sx[bl * 193 + c] = x[(size_t)(b0 + bl) * (N_NODES * 3) + n0 * 3 + c];
    }
    __syncthreads();
    #pragma unroll 4
    for (int p = 0; p < 16; p++) {
        int idx = p * 256 + tid;
        int nl = idx >> 6, bl = idx & 63;
        int n = n0 + nl;
        float sc = g_csrcs[n];
        int f0 = q16(sx[bl * 193 + nl * 3 + 0] * sc);
        int f1 = q16(sx[bl * 193 + nl * 3 + 1] * sc);
        int f2 = q16(sx[bl * 193 + nl * 3 + 2] * sc);
        unsigned long long v = (unsigned long long)(unsigned short)f0
                             | ((unsigned long long)(unsigned short)f1 << 16)
                             | ((unsigned long long)(unsigned short)f2 << 32);
        g_xqT[(size_t)n * N_BATCH + b0 + bl] = v;
    }
}

// -------- launch 4: fused gather + MLP + fc partials --------
// Grid = 128 node-chunks x 4 group-pairs. CTA = 256 thr (8 warps).
// Warp handles 4 nodes x 64 batches (lane = batch): neighbor index is UNIFORM
// across the warp (broadcast LDG), feature fetch is one coalesced LDG.64 per
// edge per 32-batch group — no bank conflicts, no intra-warp divergence.
// Int accumulation => deterministic. Then per node: h = relu(y@W1+b1) via
// FFMA2 j-pairs (W1/b1 pairs broadcast from SMEM, Wfc uniform float2 LDG),
// acc += h.Wfc. CTA reduces warps in fixed order -> g_partial[batch][chunk].
__global__ __launch_bounds__(256) void k_mainT(const float* __restrict__ W1,
                                               const float* __restrict__ b1,
                                               const float* __restrict__ Wfc) {
    __shared__ unsigned long long sw0[32], sw1[32], sw2[32], swb[32];
    __shared__ float red[8][64];
    int tid = threadIdx.x;
    int chunk = blockIdx.x >> 2;
    int gp = blockIdx.x & 3;
    if (tid < 32) {
        int j = 2 * tid;
        sw0[tid] = packf2(W1[j],        W1[j + 1]);
        sw1[tid] = packf2(W1[64 + j],   W1[64 + j + 1]);
        sw2[tid] = packf2(W1[128 + j],  W1[128 + j + 1]);
        swb[tid] = packf2(b1[j],        b1[j + 1]);
    }
    __syncthreads();
    int w = tid >> 5, L = tid & 31;
    int bA = gp * 64 + L;                    // group A batch; group B = bA+32
    const unsigned long long* xb = g_xqT + bA;
    float accA = 0.f, accB = 0.f;
    #pragma unroll 1
    for (int ni = 0; ni < 4; ni++) {
        int n = chunk * 32 + w * 4 + ni;
        int k0 = g_rowptr[n], k1 = g_rowptr[n + 1];
        int aA0 = 0, aA1 = 0, aA2 = 0, aB0 = 0, aB1 = 0, aB2 = 0;
        #pragma unroll 4
        for (int k = k0; k < k1; k++) {
            int s = (int)g_col[k];
            unsigned long long vA = xb[(size_t)s * N_BATCH];
            unsigned long long vB = xb[(size_t)s * N_BATCH + 32];
            aA0 += (int)(short)vA;
            aA1 += (int)(short)(vA >> 16);
            aA2 += (int)(short)(vA >> 32);
            aB0 += (int)(short)vB;
            aB1 += (int)(short)(vB >> 16);
            aB2 += (int)(short)(vB >> 32);
        }
        float cd = g_cdsts[n];
        float yA0 = aA0 * cd, yA1 = aA1 * cd, yA2 = aA2 * cd;
        float yB0 = aB0 * cd, yB1 = aB1 * cd, yB2 = aB2 * cd;
        unsigned long long pA0 = packf2(yA0, yA0), pA1 = packf2(yA1, yA1), pA2 = packf2(yA2, yA2);
        unsigned long long pB0 = packf2(yB0, yB0), pB1 = packf2(yB1, yB1), pB2 = packf2(yB2, yB2);
        const float2* wfr = (const float2*)(Wfc + n * 64);
        #pragma unroll 8
        for (int j = 0; j < 32; j++) {
            float2 wf = wfr[j];                       // uniform LDG.64 (broadcast)
            unsigned long long hA, hB;
            FMA_F32X2(hA, pA0, sw0[j], swb[j]);
            FMA_F32X2(hA, pA1, sw1[j], hA);
            FMA_F32X2(hA, pA2, sw2[j], hA);
            FMA_F32X2(hB, pB0, sw0[j], swb[j]);
            FMA_F32X2(hB, pB1, sw1[j], hB);
            FMA_F32X2(hB, pB2, sw2[j], hB);
            float a0, a1, c0, c1;
            unpackf2(hA, a0, a1);
            unpackf2(hB, c0, c1);
            accA = fmaf(fmaxf(a0, 0.f), wf.x, accA);
            accA = fmaf(fmaxf(a1, 0.f), wf.y, accA);
            accB = fmaf(fmaxf(c0, 0.f), wf.x, accB);
            accB = fmaf(fmaxf(c1, 0.f), wf.y, accB);
        }
    }
    red[w][L] = accA;
    red[w][32 + L] = accB;
    __syncthreads();
    if (tid < 64) {
        float s = 0.f;
        #pragma unroll
        for (int ww = 0; ww < 8; ww++) s += red[ww][tid];   // fixed order
        g_partial[(gp * 64 + tid) * NCHUNKS + chunk] = s;
    }
}

// -------- launch 5: reduce 128 chunk-partials per batch, sigmoid --------
__global__ __launch_bounds__(1024) void k_final(const float* __restrict__ bfc,
                                                float* __restrict__ out) {
    int b = blockIdx.x * 32 + (threadIdx.x >> 5);
    int L = threadIdx.x & 31;
    float s = 0.f;
    #pragma unroll
    for (int i = 0; i < 4; i++) s += g_partial[b * NCHUNKS + L + 32 * i];
    #pragma unroll
    for (int off = 16; off; off >>= 1) s += __shfl_xor_sync(0xffffffffu, s, off);
    if (L == 0) out[b] = 1.0f / (1.0f + expf(-(s + bfc[0])));
}

// ---------------- launch ----------------
extern "C" void kernel_launch(void* const* d_in, const int* in_sizes, int n_in,
                              void* d_out, int out_size) {
    const float* x   = (const float*)d_in[0];
    const float* W1  = (const float*)d_in[1];
    const float* b1  = (const float*)d_in[2];
    const float* Wfc = (const float*)d_in[3];
    const float* bfc = (const float*)d_in[4];
    const int*   src = (const int*)d_in[5];
    const int*   dst = (const int*)d_in[6];
    float* out = (float*)d_out;

    const int stage_smem = 64 * 193 * 4;   // 49408 B
    cudaFuncSetAttribute(k_stage, cudaFuncAttributeMaxDynamicSharedMemorySize, stage_smem);

    k_deg<<<DEG_CTAS, 1024>>>(src, dst);
    k_scan<<<1, 1024>>>();
    k_scatter<<<N_EDGES / 1024, 1024>>>(src, dst);
    k_stage<<<256, 256, stage_smem>>>(x);
    k_mainT<<<NCHUNKS * GPAIRS, 256>>>(W1, b1, Wfc);
    k_final<<<8, 1024>>>(bfc, out);
}

// round 8
// speedup vs baseline: 2.7872x; 1.1144x over previous
#include <cuda_runtime.h>
#include <math.h>
#include <stdint.h>

#define N_NODES 4096
#define N_EDGES 65536
#define N_BATCH 256
#define DEG_CTAS 16
#define FPSCALE 4096.0f            // 2^12 fixed-point scale (s16 range)
#define NCHUNKS 512                // node chunks of 8 (1 node per warp)
#define GPAIRS 4                   // 4 batch-groups x 64 batches = 256

// ---------------- scratch (no device allocations allowed) ----------------
__device__ int g_part_in[DEG_CTAS * N_NODES];
__device__ int g_part_out[DEG_CTAS * N_NODES];
__device__ int g_rowptr[N_NODES + 1];
__device__ int g_cursor[N_NODES];
__device__ unsigned short g_col[N_EDGES];
__device__ float g_csrcs[N_NODES];   // rsqrt(deg_out) * 2^12
__device__ float g_cdsts[N_NODES];   // rsqrt(deg_in)  * 2^-12
__device__ unsigned long long g_xqT[(size_t)N_NODES * N_BATCH];  // [node][batch] 3x s16
__device__ float g_partial[N_BATCH * NCHUNKS];

// packed f32x2 helpers
#define FMA_F32X2(out, a, b, c) \
    asm("fma.rn.f32x2 %0, %1, %2, %3;" : "=l"(out) : "l"(a), "l"(b), "l"(c))
__device__ __forceinline__ unsigned long long packf2(float lo, float hi) {
    unsigned long long r;
    asm("mov.b64 %0, {%1, %2};" : "=l"(r) : "f"(lo), "f"(hi));
    return r;
}
__device__ __forceinline__ void unpackf2(unsigned long long v, float& lo, float& hi) {
    asm("mov.b64 {%0, %1}, %2;" : "=f"(lo), "=f"(hi) : "l"(v));
}
__device__ __forceinline__ int q16(float v) {
    int f = __float2int_rn(v);
    f = max(-32768, min(32767, f));
    return f;
}

// -------- launch 0: per-CTA smem histogram of in/out degrees --------
__global__ __launch_bounds__(1024) void k_deg(const int* __restrict__ src,
                                              const int* __restrict__ dst) {
    __shared__ int sh_in[N_NODES];
    __shared__ int sh_out[N_NODES];
    int tid = threadIdx.x, cta = blockIdx.x;
    for (int i = tid; i < N_NODES; i += 1024) { sh_in[i] = 0; sh_out[i] = 0; }
    __syncthreads();
    int e0 = cta * (N_EDGES / DEG_CTAS);
    for (int i = tid; i < N_EDGES / DEG_CTAS; i += 1024) {
        atomicAdd(&sh_out[src[e0 + i]], 1);
        atomicAdd(&sh_in[dst[e0 + i]], 1);
    }
    __syncthreads();
    for (int i = tid; i < N_NODES; i += 1024) {
        g_part_in[cta * N_NODES + i] = sh_in[i];
        g_part_out[cta * N_NODES + i] = sh_out[i];
    }
}

// -------- launch 1: reduce partials, scan rowptr, norms, zero cursor --------
__global__ __launch_bounds__(1024) void k_scan() {
    __shared__ int ssum[1024];
    int t = threadIdx.x;
    int din[4], dout[4];
    #pragma unroll
    for (int j = 0; j < 4; j++) { din[j] = 0; dout[j] = 0; }
    #pragma unroll
    for (int c = 0; c < DEG_CTAS; c++) {
        #pragma unroll
        for (int j = 0; j < 4; j++) {
            din[j]  += g_part_in[c * N_NODES + 4 * t + j];
            dout[j] += g_part_out[c * N_NODES + 4 * t + j];
        }
    }
    int s = din[0] + din[1] + din[2] + din[3];
    ssum[t] = s;
    __syncthreads();
    for (int off = 1; off < 1024; off <<= 1) {
        int v = (t >= off) ? ssum[t - off] : 0;
        __syncthreads();
        ssum[t] += v;
        __syncthreads();
    }
    int excl = ssum[t] - s;
    g_rowptr[4 * t + 0] = excl;
    g_rowptr[4 * t + 1] = excl + din[0];
    g_rowptr[4 * t + 2] = excl + din[0] + din[1];
    g_rowptr[4 * t + 3] = excl + din[0] + din[1] + din[2];
    if (t == 1023) g_rowptr[N_NODES] = ssum[1023];
    #pragma unroll
    for (int j = 0; j < 4; j++) {
        int n = 4 * t + j;
        g_csrcs[n] = rsqrtf(fmaxf((float)dout[j], 1.0f)) * FPSCALE;
        g_cdsts[n] = rsqrtf(fmaxf((float)din[j], 1.0f)) * (1.0f / FPSCALE);
        g_cursor[n] = 0;
    }
}

// -------- launch 2: scatter edges into CSR (order-free: sums are integer) --------
__global__ __launch_bounds__(1024) void k_scatter(const int* __restrict__ src,
                                                  const int* __restrict__ dst) {
    int e = blockIdx.x * 1024 + threadIdx.x;
    if (e < N_EDGES) {
        int d = dst[e];
        int pos = atomicAdd(&g_cursor[d], 1);
        g_col[g_rowptr[d] + pos] = (unsigned short)src[e];
    }
}

// -------- launch 3: transpose+quantize x into [node][batch] u64 (3x s16) --------
// Tile = 32 nodes x 64 batches (25KB smem) -> 512 CTAs for occupancy.
__global__ __launch_bounds__(256) void k_stage(const float* __restrict__ x) {
    extern __shared__ float sx[];   // [64][97] padded (96 cols = 32 nodes * 3)
    int n0 = (blockIdx.x >> 2) * 32;
    int b0 = (blockIdx.x & 3) * 64;
    int tid = threadIdx.x;
    for (int i = tid; i < 64 * 96; i += 256) {
        int bl = i / 96, c = i - bl * 96;
        sx[bl * 97 + c] = x[(size_t)(b0 + bl) * (N_NODES * 3) + n0 * 3 + c];
    }
    __syncthreads();
    #pragma unroll
    for (int p = 0; p < 8; p++) {
        int idx = p * 256 + tid;
        int nl = idx >> 6, bl = idx & 63;
        int n = n0 + nl;
        float sc = g_csrcs[n];
        int f0 = q16(sx[bl * 97 + nl * 3 + 0] * sc);
        int f1 = q16(sx[bl * 97 + nl * 3 + 1] * sc);
        int f2 = q16(sx[bl * 97 + nl * 3 + 2] * sc);
        unsigned long long v = (unsigned long long)(unsigned short)f0
                             | ((unsigned long long)(unsigned short)f1 << 16)
                             | ((unsigned long long)(unsigned short)f2 << 32);
        g_xqT[(size_t)n * N_BATCH + b0 + bl] = v;
    }
}

// -------- launch 4: fused gather + MLP + fc partials --------
// Grid = 512 node-chunks x 4 batch-groups, CTA = 256 thr (8 warps),
// warp = ONE node x 64 batches; lane L carries batches gp*64+2L, +2L+1.
// Per edge: uniform neighbor index + ONE coalesced LDG.128 (512B/warp),
// int32 accumulation (deterministic). Then h = relu(y@W1+b1) via FFMA2
// col-pairs, acc += h.Wfc (uniform float2 LDG). CTA reduces 8 warps in
// fixed order -> g_partial[batch][chunk].
__global__ __launch_bounds__(256) void k_mainT(const float* __restrict__ W1,
                                               const float* __restrict__ b1,
                                               const float* __restrict__ Wfc) {
    __shared__ unsigned long long sw0[32], sw1[32], sw2[32], swb[32];
    __shared__ float red[8][64];
    int tid = threadIdx.x;
    int chunk = blockIdx.x >> 2;
    int gp = blockIdx.x & 3;
    if (tid < 32) {
        int j = 2 * tid;
        sw0[tid] = packf2(W1[j],        W1[j + 1]);
        sw1[tid] = packf2(W1[64 + j],   W1[64 + j + 1]);
        sw2[tid] = packf2(W1[128 + j],  W1[128 + j + 1]);
        swb[tid] = packf2(b1[j],        b1[j + 1]);
    }
    __syncthreads();
    int w = tid >> 5, L = tid & 31;
    int bA = gp * 64 + 2 * L;                 // lane's batch pair (bA, bA+1)
    const unsigned long long* xb = g_xqT + bA;

    int n = chunk * 8 + w;
    int k0 = g_rowptr[n], k1 = g_rowptr[n + 1];
    int aA0 = 0, aA1 = 0, aA2 = 0, aB0 = 0, aB1 = 0, aB2 = 0;
    #pragma unroll 4
    for (int k = k0; k < k1; k++) {
        int s = (int)g_col[k];
        ulonglong2 v = *(const ulonglong2*)(xb + (size_t)s * N_BATCH);
        aA0 += (int)(short)v.x;
        aA1 += (int)(short)(v.x >> 16);
        aA2 += (int)(short)(v.x >> 32);
        aB0 += (int)(short)v.y;
        aB1 += (int)(short)(v.y >> 16);
        aB2 += (int)(short)(v.y >> 32);
    }
    float cd = g_cdsts[n];
    float yA0 = aA0 * cd, yA1 = aA1 * cd, yA2 = aA2 * cd;
    float yB0 = aB0 * cd, yB1 = aB1 * cd, yB2 = aB2 * cd;
    unsigned long long pA0 = packf2(yA0, yA0), pA1 = packf2(yA1, yA1), pA2 = packf2(yA2, yA2);
    unsigned long long pB0 = packf2(yB0, yB0), pB1 = packf2(yB1, yB1), pB2 = packf2(yB2, yB2);

    float accA = 0.f, accB = 0.f;
    const float2* wfr = (const float2*)(Wfc + n * 64);
    #pragma unroll 8
    for (int j = 0; j < 32; j++) {
        float2 wf = wfr[j];                   // uniform LDG.64 (broadcast)
        unsigned long long hA, hB;
        FMA_F32X2(hA, pA0, sw0[j], swb[j]);
        FMA_F32X2(hA, pA1, sw1[j], hA);
        FMA_F32X2(hA, pA2, sw2[j], hA);
        FMA_F32X2(hB, pB0, sw0[j], swb[j]);
        FMA_F32X2(hB, pB1, sw1[j], hB);
        FMA_F32X2(hB, pB2, sw2[j], hB);
        float a0, a1, c0, c1;
        unpackf2(hA, a0, a1);
        unpackf2(hB, c0, c1);
        accA = fmaf(fmaxf(a0, 0.f), wf.x, accA);
        accA = fmaf(fmaxf(a1, 0.f), wf.y, accA);
        accB = fmaf(fmaxf(c0, 0.f), wf.x, accB);
        accB = fmaf(fmaxf(c1, 0.f), wf.y, accB);
    }
    red[w][2 * L]     = accA;
    red[w][2 * L + 1] = accB;
    __syncthreads();
    if (tid < 64) {
        float s = 0.f;
        #pragma unroll
        for (int ww = 0; ww < 8; ww++) s += red[ww][tid];   // fixed order
        g_partial[(gp * 64 + tid) * NCHUNKS + chunk] = s;
    }
}

// -------- launch 5: reduce 512 chunk-partials per batch, sigmoid --------
__global__ __launch_bounds__(1024) void k_final(const float* __restrict__ bfc,
                                                float* __restrict__ out) {
    int b = blockIdx.x * 32 + (threadIdx.x >> 5);
    int L = threadIdx.x & 31;
    float s = 0.f;
    #pragma unroll
    for (int i = 0; i < 16; i++) s += g_partial[b * NCHUNKS + L + 32 * i];
    #pragma unroll
    for (int off = 16; off; off >>= 1) s += __shfl_xor_sync(0xffffffffu, s, off);
    if (L == 0) out[b] = 1.0f / (1.0f + expf(-(s + bfc[0])));
}

// ---------------- launch ----------------
extern "C" void kernel_launch(void* const* d_in, const int* in_sizes, int n_in,
                              void* d_out, int out_size) {
    const float* x   = (const float*)d_in[0];
    const float* W1  = (const float*)d_in[1];
    const float* b1  = (const float*)d_in[2];
    const float* Wfc = (const float*)d_in[3];
    const float* bfc = (const float*)d_in[4];
    const int*   src = (const int*)d_in[5];
    const int*   dst = (const int*)d_in[6];
    float* out = (float*)d_out;

    const int stage_smem = 64 * 97 * 4;   // 24832 B
    cudaFuncSetAttribute(k_stage, cudaFuncAttributeMaxDynamicSharedMemorySize, stage_smem);

    k_deg<<<DEG_CTAS, 1024>>>(src, dst);
    k_scan<<<1, 1024>>>();
    k_scatter<<<N_EDGES / 1024, 1024>>>(src, dst);
    k_stage<<<512, 256, stage_smem>>>(x);
    k_mainT<<<NCHUNKS * GPAIRS, 256>>>(W1, b1, Wfc);
    k_final<<<8, 1024>>>(bfc, out);
}